// round 10
// baseline (speedup 1.0000x reference)
#include <cuda_runtime.h>
#include <cuda_fp16.h>

// Problem constants (fixed by the reference)
#define NPTS 1048576          // N = 2^20
#define HW   300              // X = Y = Z = 300
#define NC   16               // channels
#define PLANE_CELLS (HW * HW)           // 90000
#define PLANE_ELEMS (PLANE_CELLS * NC)  // 1,440,000 elems

#define BPS 296               // blocks per slot; 3*296 = 888 = 6 * 148 SMs
#define TPB 128               // threads per block
#define NGROUPS (NPTS / 32)   // 32768 point-groups of 32

// Channel-last scratch, fp16 (all interpolation math stays fp32).
// planes[0]=xy, [1]=yz, [2]=xz ; lines[0]=x, [1]=y, [2]=z
__device__ __align__(16) __half g_planes[3][PLANE_ELEMS];  // 8.64 MB
__device__ __align__(16) __half g_lines[3][HW * NC];       // 28.8 KB

// ---------------------------------------------------------------------------
// Transpose (C,H,W) f32 -> (H*W, C) f16.
// ---------------------------------------------------------------------------
__global__ __launch_bounds__(256) void transpose_planes(
    const float* __restrict__ p_xy,
    const float* __restrict__ p_yz,
    const float* __restrict__ p_xz)
{
    int tid = blockIdx.x * blockDim.x + threadIdx.x;
    if (tid >= 3 * PLANE_CELLS) return;
    int p    = tid / PLANE_CELLS;
    int cell = tid - p * PLANE_CELLS;
    const float* __restrict__ src = (p == 0) ? p_xy : (p == 1) ? p_yz : p_xz;

    __half2 h[8];
#pragma unroll
    for (int i = 0; i < 8; i++) {
        float a = src[(2 * i + 0) * PLANE_CELLS + cell];
        float b = src[(2 * i + 1) * PLANE_CELLS + cell];
        h[i] = __floats2half2_rn(a, b);
    }
    uint4* dst = reinterpret_cast<uint4*>(g_planes[p] + cell * NC);
    dst[0] = reinterpret_cast<const uint4*>(h)[0];
    dst[1] = reinterpret_cast<const uint4*>(h)[1];
}

__global__ __launch_bounds__(256) void transpose_lines(
    const float* __restrict__ l_x,
    const float* __restrict__ l_y,
    const float* __restrict__ l_z)
{
    int tid = blockIdx.x * blockDim.x + threadIdx.x;
    if (tid >= 3 * HW) return;
    int l = tid / HW;
    int x = tid - l * HW;
    const float* __restrict__ src = (l == 0) ? l_x : (l == 1) ? l_y : l_z;

    __half2 h[8];
#pragma unroll
    for (int i = 0; i < 8; i++) {
        h[i] = __floats2half2_rn(src[(2 * i + 0) * HW + x],
                                 src[(2 * i + 1) * HW + x]);
    }
    uint4* dst = reinterpret_cast<uint4*>(g_lines[l] + x * NC);
    dst[0] = reinterpret_cast<const uint4*>(h)[0];
    dst[1] = reinterpret_cast<const uint4*>(h)[1];
}

// Widen 4 packed fp16 (held as uint2 raw) to fp32.
__device__ __forceinline__ float4 cvt4(uint2 u)
{
    float2 f0 = __half22float2(*reinterpret_cast<const __half2*>(&u.x));
    float2 f1 = __half22float2(*reinterpret_cast<const __half2*>(&u.y));
    return make_float4(f0.x, f0.y, f1.x, f1.y);
}

__device__ __forceinline__ float4 ldh4s(const __half* p)   // smem fp16 quad
{
    return cvt4(*reinterpret_cast<const uint2*>(p));
}

// Per-group index/weight state.
struct GIdx {
    int r0o0, r0o1, r1o0, r1o1;       // plane element offsets of the 4 corners
    float w00, w01, w10, w11;         // bilinear weights
    int l0, l1;                        // line taps
    float lw0, lw1;
    int n;                             // point index
};

__device__ __forceinline__ GIdx make_gidx(float2 pc, float2 lc, int n, int c4)
{
    GIdx s; s.n = n;
    float ix = (pc.x + 1.0f) * 0.5f * (float)(HW - 1);
    float iy = (pc.y + 1.0f) * 0.5f * (float)(HW - 1);
    float ix0f = floorf(ix), iy0f = floorf(iy);
    float wx = ix - ix0f;
    float wy = iy - iy0f;
    int ix0 = min(max((int)ix0f, 0), HW - 1);
    int ix1 = min(ix0 + 1, HW - 1);
    int iy0 = min(max((int)iy0f, 0), HW - 1);
    int iy1 = min(iy0 + 1, HW - 1);
    s.w00 = (1.0f - wx) * (1.0f - wy);
    s.w01 = wx * (1.0f - wy);
    s.w10 = (1.0f - wx) * wy;
    s.w11 = wx * wy;
    int r0 = iy0 * (HW * NC), r1 = iy1 * (HW * NC);
    int o0 = ix0 * NC + c4,   o1 = ix1 * NC + c4;
    s.r0o0 = r0 + o0; s.r0o1 = r0 + o1;
    s.r1o0 = r1 + o0; s.r1o1 = r1 + o1;

    float ly = (lc.y + 1.0f) * 0.5f * (float)(HW - 1);
    float ly0f = floorf(ly);
    float wly = ly - ly0f;
    s.l0 = min(max((int)ly0f, 0), HW - 1);
    s.l1 = min(s.l0 + 1, HW - 1);
    s.lw0 = 1.0f - wly; s.lw1 = wly;
    return s;
}

// ---------------------------------------------------------------------------
// Main gather, software-pipelined x2: two point-groups per iteration; all 8
// plane LDGs issued as raw uint2 before any conversion/consumption, doubling
// per-warp MLP and overlapping group B's memory wait with group A's compute.
// Cooperative 4-lane teams (lane owns 4 channels); line taps from smem.
//   slot 0: out_x = bilerp(plane_yz, cp[1]) * lerp(line_x, cl[0].y)
//   slot 1: out_y = bilerp(plane_xz, cp[2]) * lerp(line_y, cl[1].y)
//   slot 2: out_z = bilerp(plane_xy, cp[0]) * lerp(line_z, cl[2].y)
// ---------------------------------------------------------------------------
__global__ __launch_bounds__(TPB, 6) void sample_kernel(
    const float2* __restrict__ cp,   // coords_plane, (3, N) float2
    const float2* __restrict__ cl,   // coords_line,  (3, N) float2
    float*        __restrict__ out)  // (3, N, 16)
{
    __shared__ __align__(16) __half s_line[HW * NC];   // 9.6 KB

    int slot = blockIdx.x / BPS;
    int blk  = blockIdx.x - slot * BPS;
    int pi   = (slot == 0) ? 1 : (slot == 1) ? 2 : 0;  // transposed plane idx

    // Copy this slot's line table into smem (600 x uint4).
    {
        const uint4* __restrict__ src = reinterpret_cast<const uint4*>(g_lines[slot]);
        uint4* dst = reinterpret_cast<uint4*>(s_line);
        for (int i = threadIdx.x; i < (HW * NC) / 8; i += TPB)
            dst[i] = src[i];
    }
    __syncthreads();

    const __half* __restrict__ P = g_planes[pi];
    const float2* __restrict__ CP = cp + pi * NPTS;
    const float2* __restrict__ CL = cl + slot * NPTS;
    float* __restrict__ O = out + (size_t)slot * NPTS * NC;

    int c4   = (threadIdx.x & 3) * 4;   // channel offset
    int pofs = threadIdx.x >> 2;        // point within group

    for (int g = blk; g < NGROUPS; g += 2 * BPS) {
        int gB = g + BPS;
        bool hasB = (gB < NGROUPS);
        int nA = g * 32 + pofs;
        int nB = hasB ? (gB * 32 + pofs) : nA;

        // Batch both groups' coord loads up front.
        float2 pcA = CP[nA], lcA = CL[nA];
        float2 pcB = CP[nB], lcB = CL[nB];

        GIdx A = make_gidx(pcA, lcA, nA, c4);
        GIdx B = make_gidx(pcB, lcB, nB, c4);

        // Issue all 8 plane gathers (raw) before consuming any.
        uint2 qA00 = *reinterpret_cast<const uint2*>(P + A.r0o0);
        uint2 qA01 = *reinterpret_cast<const uint2*>(P + A.r0o1);
        uint2 qA10 = *reinterpret_cast<const uint2*>(P + A.r1o0);
        uint2 qA11 = *reinterpret_cast<const uint2*>(P + A.r1o1);
        uint2 qB00 = *reinterpret_cast<const uint2*>(P + B.r0o0);
        uint2 qB01 = *reinterpret_cast<const uint2*>(P + B.r0o1);
        uint2 qB10 = *reinterpret_cast<const uint2*>(P + B.r1o0);
        uint2 qB11 = *reinterpret_cast<const uint2*>(P + B.r1o1);

        // ---- consume A ----
        {
            float4 v00 = cvt4(qA00), v01 = cvt4(qA01);
            float4 v10 = cvt4(qA10), v11 = cvt4(qA11);
            float4 a0 = ldh4s(s_line + A.l0 * NC + c4);
            float4 a1 = ldh4s(s_line + A.l1 * NC + c4);
            float4 r;
            r.x = (v00.x * A.w00 + v01.x * A.w01 + v10.x * A.w10 + v11.x * A.w11)
                  * (a0.x * A.lw0 + a1.x * A.lw1);
            r.y = (v00.y * A.w00 + v01.y * A.w01 + v10.y * A.w10 + v11.y * A.w11)
                  * (a0.y * A.lw0 + a1.y * A.lw1);
            r.z = (v00.z * A.w00 + v01.z * A.w01 + v10.z * A.w10 + v11.z * A.w11)
                  * (a0.z * A.lw0 + a1.z * A.lw1);
            r.w = (v00.w * A.w00 + v01.w * A.w01 + v10.w * A.w10 + v11.w * A.w11)
                  * (a0.w * A.lw0 + a1.w * A.lw1);
            *reinterpret_cast<float4*>(O + (size_t)A.n * NC + c4) = r;
        }

        // ---- consume B ----
        if (hasB) {
            float4 v00 = cvt4(qB00), v01 = cvt4(qB01);
            float4 v10 = cvt4(qB10), v11 = cvt4(qB11);
            float4 a0 = ldh4s(s_line + B.l0 * NC + c4);
            float4 a1 = ldh4s(s_line + B.l1 * NC + c4);
            float4 r;
            r.x = (v00.x * B.w00 + v01.x * B.w01 + v10.x * B.w10 + v11.x * B.w11)
                  * (a0.x * B.lw0 + a1.x * B.lw1);
            r.y = (v00.y * B.w00 + v01.y * B.w01 + v10.y * B.w10 + v11.y * B.w11)
                  * (a0.y * B.lw0 + a1.y * B.lw1);
            r.z = (v00.z * B.w00 + v01.z * B.w01 + v10.z * B.w10 + v11.z * B.w11)
                  * (a0.z * B.lw0 + a1.z * B.lw1);
            r.w = (v00.w * B.w00 + v01.w * B.w01 + v10.w * B.w10 + v11.w * B.w11)
                  * (a0.w * B.lw0 + a1.w * B.lw1);
            *reinterpret_cast<float4*>(O + (size_t)B.n * NC + c4) = r;
        }
    }
}

// ---------------------------------------------------------------------------
// Inputs (metadata order):
//   0: coords_plane (3,1,N,1,2)  1: coords_line (3,1,N,1,2)
//   2: plane_xy  3: plane_yz  4: plane_xz
//   5: line_x    6: line_y    7: line_z
// Output: concat(out_x, out_y, out_z), each (N,16) f32.
// ---------------------------------------------------------------------------
extern "C" void kernel_launch(void* const* d_in, const int* in_sizes, int n_in,
                              void* d_out, int out_size)
{
    (void)in_sizes; (void)n_in; (void)out_size;

    transpose_planes<<<(3 * PLANE_CELLS + 255) / 256, 256>>>(
        (const float*)d_in[2], (const float*)d_in[3], (const float*)d_in[4]);
    transpose_lines<<<(3 * HW + 255) / 256, 256>>>(
        (const float*)d_in[5], (const float*)d_in[6], (const float*)d_in[7]);

    sample_kernel<<<3 * BPS, TPB>>>(
        (const float2*)d_in[0], (const float2*)d_in[1], (float*)d_out);
}